// round 15
// baseline (speedup 1.0000x reference)
#include <cuda_runtime.h>
#include <cstdint>

// ---------------- static scratch (no allocations allowed) ----------------
#define MAXN0 600000
__device__ float g_x0[MAXN0 * 16];
__device__ float g_x1[MAXN0 * 16];
__device__ float g_x2[MAXN0 * 32];
__device__ float g_r0[MAXN0 * 32];
__device__ float g_r1[MAXN0 * 32];
__device__ int   g_gi0[27 * MAXN0];
__device__ int   g_gid[8 * MAXN0];
__device__ int   g_gi1[27 * MAXN0];

typedef unsigned long long u64;
union F2U { u64 u; float2 f; };

__device__ __forceinline__ u64 bcast2(float s) {
    u64 r; asm("mov.b64 %0, {%1, %1};" : "=l"(r) : "r"(__float_as_uint(s))); return r;
}
__device__ __forceinline__ void ffma2(u64& a, u64 x, u64 w) {
    asm("fma.rn.f32x2 %0, %1, %2, %3;" : "=l"(a) : "l"(x), "l"(w), "l"(a));
}
__device__ __forceinline__ u64 packf2(float lo, float hi) {
    u64 r; asm("mov.b64 %0, {%1, %2};" : "=l"(r) : "r"(__float_as_uint(lo)), "r"(__float_as_uint(hi))); return r;
}

// ---------------- inverse-map build ----------------
__global__ void build_gi(const int* __restrict__ kin, const int* __restrict__ kout,
                         int* __restrict__ gi, int P, int n) {
    const int k = blockIdx.y;
    int p = blockIdx.x * blockDim.x + threadIdx.x;
    if (p >= P) return;
    const size_t base = (size_t)k * P;
    int j = kout[base + p];
    if (j < n) gi[(size_t)k * n + j] = kin[base + p];
}

// ---------------- conv 1->16: two output rows per thread (R13) ----------
__global__ __launch_bounds__(256) void conv1_16j2(const float* __restrict__ x,
        const float* __restrict__ W, const int* __restrict__ gi,
        const float* __restrict__ b, float* __restrict__ out,
        float* __restrict__ cache, int n) {
    __shared__ float Ws[27 * 16];
    for (int t = threadIdx.x; t < 27 * 16; t += 256) Ws[t] = W[t];
    __syncthreads();
    const int tid = threadIdx.x;
    const int j0 = blockIdx.x * 512 + tid;
    const int j1 = j0 + 256;
    const bool jv1 = j1 < n;
    if (j0 >= n) return;
    float acc0[16], acc1[16];
#pragma unroll
    for (int c = 0; c < 16; ++c) { float bb = __ldg(b + c); acc0[c] = bb; acc1[c] = bb; }
#pragma unroll
    for (int kb = 0; kb < 27; kb += 9) {
        int id0[9], id1[9];
#pragma unroll
        for (int t = 0; t < 9; ++t) {
            id0[t] = __ldg(gi + (size_t)(kb + t) * n + j0);
            id1[t] = jv1 ? __ldg(gi + (size_t)(kb + t) * n + j1) : -1;
        }
        float xv0[9], xv1[9];
#pragma unroll
        for (int t = 0; t < 9; ++t) {
            xv0[t] = (id0[t] >= 0) ? __ldg(x + id0[t]) : 0.f;
            xv1[t] = (id1[t] >= 0) ? __ldg(x + id1[t]) : 0.f;
        }
#pragma unroll
        for (int t = 0; t < 9; ++t) {
#pragma unroll
            for (int c = 0; c < 16; ++c) {
                acc0[c] += xv0[t] * Ws[(kb + t) * 16 + c];
                acc1[c] += xv1[t] * Ws[(kb + t) * 16 + c];
            }
        }
    }
    {
        float4* o4 = (float4*)(out + (size_t)j0 * 16);
        float4* c4 = (float4*)(cache + (size_t)j0 * 16);
#pragma unroll
        for (int r = 0; r < 4; ++r) {
            float4 v = make_float4(fmaxf(acc0[4*r], 0.f), fmaxf(acc0[4*r+1], 0.f),
                                   fmaxf(acc0[4*r+2], 0.f), fmaxf(acc0[4*r+3], 0.f));
            o4[r] = v; c4[r] = v;
        }
    }
    if (jv1) {
        float4* o4 = (float4*)(out + (size_t)j1 * 16);
        float4* c4 = (float4*)(cache + (size_t)j1 * 16);
#pragma unroll
        for (int r = 0; r < 4; ++r) {
            float4 v = make_float4(fmaxf(acc1[4*r], 0.f), fmaxf(acc1[4*r+1], 0.f),
                                   fmaxf(acc1[4*r+2], 0.f), fmaxf(acc1[4*r+3], 0.f));
            o4[r] = v; c4[r] = v;
        }
    }
}

// ====== conv 16->16 (K=27): four rows/thread, branch-free k-body ========
__global__ __launch_bounds__(256, 2) void conv16_16j4(const float* __restrict__ x,
        const float* __restrict__ W, const int* __restrict__ gi,
        const float* __restrict__ b, float* __restrict__ out, int n) {
    __shared__ float4 Ws4[27 * 64];          // 27 KB
    const float4* Wg = (const float4*)W;
    for (int t = threadIdx.x; t < 27 * 64; t += 256) Ws4[t] = Wg[t];
    __syncthreads();
    const ulonglong2* Wu = (const ulonglong2*)Ws4;
    const int tid = threadIdx.x;
    int j[4];
    j[0] = blockIdx.x * 1024 + tid;
    j[1] = j[0] + 256; j[2] = j[0] + 512; j[3] = j[0] + 768;

    u64 acc[32];                              // 8 u64 per row
    {
        const float4* b4 = (const float4*)b;
#pragma unroll
        for (int r = 0; r < 4; ++r) {
            float4 bb = __ldg(b4 + r);
            u64 lo = packf2(bb.x, bb.y), hi = packf2(bb.z, bb.w);
#pragma unroll
            for (int o = 0; o < 4; ++o) { acc[o*8 + 2*r] = lo; acc[o*8 + 2*r + 1] = hi; }
        }
    }
    int a[4];
#pragma unroll
    for (int o = 0; o < 4; ++o) a[o] = (j[o] < n) ? __ldg(gi + j[o]) : -1;

#pragma unroll 3
    for (int k = 0; k < 27; ++k) {
        int i[4];
#pragma unroll
        for (int o = 0; o < 4; ++o) {
            i[o] = a[o];
            a[o] = (k < 26 && j[o] < n) ? __ldg(gi + (size_t)(k + 1) * n + j[o]) : -1;
        }
        const ulonglong2* Wk = Wu + (size_t)k * 64;
#pragma unroll
        for (int h = 0; h < 2; ++h) {         // input-channel halves (8 cc each)
            float4 X[4][2];
#pragma unroll
            for (int o = 0; o < 4; ++o) {
                const float4* xr = (const float4*)(x + (size_t)(i[o] < 0 ? 0 : i[o]) * 16) + h * 2;
#pragma unroll
                for (int q = 0; q < 2; ++q)
                    X[o][q] = (i[o] >= 0) ? __ldg(xr + q) : make_float4(0.f, 0.f, 0.f, 0.f);
            }
#pragma unroll
            for (int q = 0; q < 2; ++q) {
#pragma unroll
                for (int s = 0; s < 4; ++s) {
                    const int cc = h * 8 + q * 4 + s;
                    u64 xx[4];
#pragma unroll
                    for (int o = 0; o < 4; ++o) {
                        float xs = (s == 0) ? X[o][q].x : (s == 1) ? X[o][q].y
                                 : (s == 2) ? X[o][q].z : X[o][q].w;
                        xx[o] = bcast2(xs);
                    }
#pragma unroll
                    for (int r = 0; r < 4; ++r) {
                        ulonglong2 wp = Wk[cc * 4 + r];
#pragma unroll
                        for (int o = 0; o < 4; ++o) {
                            ffma2(acc[o*8 + 2*r],     xx[o], wp.x);
                            ffma2(acc[o*8 + 2*r + 1], xx[o], wp.y);
                        }
                    }
                }
            }
        }
    }
#pragma unroll
    for (int o = 0; o < 4; ++o) {
        if (j[o] >= n) continue;
        const u64* ap = acc + o * 8;
        float4* o4 = (float4*)(out + (size_t)j[o] * 16);
#pragma unroll
        for (int r = 0; r < 4; ++r) {
            F2U a0u, a1u; a0u.u = ap[2*r]; a1u.u = ap[2*r+1];
            o4[r] = make_float4(fmaxf(a0u.f.x, 0.f), fmaxf(a0u.f.y, 0.f),
                                fmaxf(a1u.f.x, 0.f), fmaxf(a1u.f.y, 0.f));
        }
    }
}

// ====== conv 16->32 (K=8): two rows/thread, branch-free k-body ==========
__global__ __launch_bounds__(256, 2) void conv16_32j2(const float* __restrict__ x,
        const float* __restrict__ W, const int* __restrict__ gi,
        const float* __restrict__ b, float* __restrict__ out, int n) {
    __shared__ float4 Ws4[8 * 128];          // 16 KB
    const float4* Wg = (const float4*)W;
    for (int t = threadIdx.x; t < 8 * 128; t += 256) Ws4[t] = Wg[t];
    __syncthreads();
    const ulonglong2* Wu = (const ulonglong2*)Ws4;
    const int tid = threadIdx.x;
    const int j0 = blockIdx.x * 512 + tid;
    const int j1 = j0 + 256;
    const bool jv0 = j0 < n, jv1 = j1 < n;

    u64 acc[32];
    {
        const float4* b4 = (const float4*)b;
#pragma unroll
        for (int r = 0; r < 8; ++r) {
            float4 bb = __ldg(b4 + r);
            u64 lo = packf2(bb.x, bb.y), hi = packf2(bb.z, bb.w);
            acc[2*r] = lo; acc[2*r+1] = hi;
            acc[16 + 2*r] = lo; acc[16 + 2*r+1] = hi;
        }
    }
    int a0 = jv0 ? __ldg(gi + j0) : -1;
    int a1 = jv1 ? __ldg(gi + j1) : -1;
#pragma unroll 2
    for (int k = 0; k < 8; ++k) {
        const int i0 = a0, i1 = a1;
        a0 = (k < 7 && jv0) ? __ldg(gi + (size_t)(k + 1) * n + j0) : -1;
        a1 = (k < 7 && jv1) ? __ldg(gi + (size_t)(k + 1) * n + j1) : -1;
        const float4* xr0 = (const float4*)(x + (size_t)(i0 < 0 ? 0 : i0) * 16);
        const float4* xr1 = (const float4*)(x + (size_t)(i1 < 0 ? 0 : i1) * 16);
        float4 X0[4], X1[4];
#pragma unroll
        for (int q = 0; q < 4; ++q) {
            X0[q] = (i0 >= 0) ? __ldg(xr0 + q) : make_float4(0.f, 0.f, 0.f, 0.f);
            X1[q] = (i1 >= 0) ? __ldg(xr1 + q) : make_float4(0.f, 0.f, 0.f, 0.f);
        }
        const ulonglong2* Wk = Wu + (size_t)k * 128;
#pragma unroll
        for (int q = 0; q < 4; ++q) {
            float xs0[4] = {X0[q].x, X0[q].y, X0[q].z, X0[q].w};
            float xs1[4] = {X1[q].x, X1[q].y, X1[q].z, X1[q].w};
#pragma unroll
            for (int s = 0; s < 4; ++s) {
                int cc = q * 4 + s;
                u64 xx0 = bcast2(xs0[s]);
                u64 xx1 = bcast2(xs1[s]);
#pragma unroll
                for (int r = 0; r < 8; ++r) {
                    ulonglong2 wp = Wk[cc * 8 + r];
                    ffma2(acc[2*r],          xx0, wp.x);
                    ffma2(acc[2*r + 1],      xx0, wp.y);
                    ffma2(acc[16 + 2*r],     xx1, wp.x);
                    ffma2(acc[16 + 2*r + 1], xx1, wp.y);
                }
            }
        }
    }
#pragma unroll
    for (int o = 0; o < 2; ++o) {
        const int j = o ? j1 : j0;
        if (j >= n) continue;
        const u64* a = acc + o * 16;
        float4* o4 = (float4*)(out + (size_t)j * 32);
#pragma unroll
        for (int r = 0; r < 8; ++r) {
            F2U a0u, a1u; a0u.u = a[2*r]; a1u.u = a[2*r+1];
            o4[r] = make_float4(fmaxf(a0u.f.x, 0.f), fmaxf(a0u.f.y, 0.f),
                                fmaxf(a1u.f.x, 0.f), fmaxf(a1u.f.y, 0.f));
        }
    }
}

// ====== conv 32->32 (K=27): two rows/thread, 2 CTAs/SM, branch-free =====
template <int EPI>   // 0 = bias+relu, 1 = bias+residual, 2 = bias only
__global__ __launch_bounds__(256, 2) void conv32_32j2(const float* __restrict__ x,
        const float* __restrict__ W, const int* __restrict__ gi,
        const float* __restrict__ b, const float* __restrict__ skip,
        float* __restrict__ out, int n) {
    extern __shared__ float4 Ws4[];          // 27 * 256 float4 = 108 KB
    const float4* Wg = (const float4*)W;
    for (int t = threadIdx.x; t < 27 * 256; t += 256) Ws4[t] = Wg[t];
    __syncthreads();
    const ulonglong2* Wu = (const ulonglong2*)Ws4;
    const int tid = threadIdx.x;
    const int j0 = blockIdx.x * 512 + tid;
    const int j1 = j0 + 256;
    const bool jv0 = j0 < n, jv1 = j1 < n;

    u64 acc[32];                              // [0..15] row j0, [16..31] row j1
    {
        const float4* b4 = (const float4*)b;
#pragma unroll
        for (int r = 0; r < 8; ++r) {
            float4 bb = __ldg(b4 + r);
            u64 lo = packf2(bb.x, bb.y), hi = packf2(bb.z, bb.w);
            acc[2*r] = lo; acc[2*r+1] = hi;
            acc[16 + 2*r] = lo; acc[16 + 2*r+1] = hi;
        }
    }
    int a0 = jv0 ? __ldg(gi + j0) : -1;
    int a1 = jv1 ? __ldg(gi + j1) : -1;
#pragma unroll 3
    for (int k = 0; k < 27; ++k) {
        const int i0 = a0, i1 = a1;
        a0 = (k < 26 && jv0) ? __ldg(gi + (size_t)(k + 1) * n + j0) : -1;
        a1 = (k < 26 && jv1) ? __ldg(gi + (size_t)(k + 1) * n + j1) : -1;
        const float4* xr0 = (const float4*)(x + (size_t)(i0 < 0 ? 0 : i0) * 32);
        const float4* xr1 = (const float4*)(x + (size_t)(i1 < 0 ? 0 : i1) * 32);
        const ulonglong2* Wk = Wu + (size_t)k * 256;
#pragma unroll
        for (int h = 0; h < 2; ++h) {         // input-channel halves keep regs low
            float4 X0[4], X1[4];
#pragma unroll
            for (int q = 0; q < 4; ++q) {
                X0[q] = (i0 >= 0) ? __ldg(xr0 + h * 4 + q) : make_float4(0.f, 0.f, 0.f, 0.f);
                X1[q] = (i1 >= 0) ? __ldg(xr1 + h * 4 + q) : make_float4(0.f, 0.f, 0.f, 0.f);
            }
#pragma unroll
            for (int q = 0; q < 4; ++q) {
                float xs0[4] = {X0[q].x, X0[q].y, X0[q].z, X0[q].w};
                float xs1[4] = {X1[q].x, X1[q].y, X1[q].z, X1[q].w};
#pragma unroll
                for (int s = 0; s < 4; ++s) {
                    int cc = h * 16 + q * 4 + s;
                    u64 xx0 = bcast2(xs0[s]);
                    u64 xx1 = bcast2(xs1[s]);
#pragma unroll
                    for (int r = 0; r < 8; ++r) {
                        ulonglong2 wp = Wk[cc * 8 + r];
                        ffma2(acc[2*r],          xx0, wp.x);
                        ffma2(acc[2*r + 1],      xx0, wp.y);
                        ffma2(acc[16 + 2*r],     xx1, wp.x);
                        ffma2(acc[16 + 2*r + 1], xx1, wp.y);
                    }
                }
            }
        }
    }
#pragma unroll
    for (int o = 0; o < 2; ++o) {
        const int j = o ? j1 : j0;
        if (j >= n) continue;
        const u64* a = acc + o * 16;
        float4* o4 = (float4*)(out + (size_t)j * 32);
        const float4* s4 = (EPI == 1) ? (const float4*)(skip + (size_t)j * 32) : nullptr;
#pragma unroll
        for (int r = 0; r < 8; ++r) {
            F2U a0u, a1u; a0u.u = a[2*r]; a1u.u = a[2*r+1];
            float4 v = make_float4(a0u.f.x, a0u.f.y, a1u.f.x, a1u.f.y);
            if (EPI == 0) {
                v.x = fmaxf(v.x, 0.f); v.y = fmaxf(v.y, 0.f);
                v.z = fmaxf(v.z, 0.f); v.w = fmaxf(v.w, 0.f);
            }
            if (EPI == 1) {
                float4 sv = __ldg(s4 + r);
                v.x += sv.x; v.y += sv.y; v.z += sv.z; v.w += sv.w;
            }
            o4[r] = v;
        }
    }
}

// ---------------- host orchestration ----------------
extern "C" void kernel_launch(void* const* d_in, const int* in_sizes, int n_in,
                              void* d_out, int out_size) {
    const float* in_feats = (const float*)d_in[0];
    const float* W_first  = (const float*)d_in[1];
    const float* b_first  = (const float*)d_in[2];
    const float* W_pre    = (const float*)d_in[3];
    const float* b_pre    = (const float*)d_in[4];
    const float* W_down   = (const float*)d_in[5];
    const float* b_down   = (const float*)d_in[6];
    const float* W_r0     = (const float*)d_in[7];
    const float* b_r0     = (const float*)d_in[8];
    const float* W_r1     = (const float*)d_in[9];
    const float* b_r1     = (const float*)d_in[10];
    const float* W_fin    = (const float*)d_in[11];
    const float* b_fin    = (const float*)d_in[12];
    const int* km0_in  = (const int*)d_in[13];
    const int* km0_out = (const int*)d_in[14];
    const int* kmd_in  = (const int*)d_in[15];
    const int* kmd_out = (const int*)d_in[16];
    const int* km1_in  = (const int*)d_in[17];
    const int* km1_out = (const int*)d_in[18];

    const int n0 = in_sizes[0];
    const int P0 = in_sizes[13] / 27;
    const int Pd = in_sizes[15] / 8;
    const int P1 = in_sizes[17] / 27;
    const int n1 = (out_size - n0 * 16) / 32;

    float* out_fin    = (float*)d_out;
    float* out_cached = (float*)d_out + (size_t)n1 * 32;

    float *x0, *x1, *x2, *r0, *r1;
    int *gi0, *gid, *gi1;
    cudaGetSymbolAddress((void**)&x0, g_x0);
    cudaGetSymbolAddress((void**)&x1, g_x1);
    cudaGetSymbolAddress((void**)&x2, g_x2);
    cudaGetSymbolAddress((void**)&r0, g_r0);
    cudaGetSymbolAddress((void**)&r1, g_r1);
    cudaGetSymbolAddress((void**)&gi0, g_gi0);
    cudaGetSymbolAddress((void**)&gid, g_gid);
    cudaGetSymbolAddress((void**)&gi1, g_gi1);

    const int SMEM32 = 27 * 256 * sizeof(float4);  // 110592 B
    static bool attr_done = false;
    if (!attr_done) {
        cudaFuncSetAttribute(conv32_32j2<0>, cudaFuncAttributeMaxDynamicSharedMemorySize, SMEM32);
        cudaFuncSetAttribute(conv32_32j2<1>, cudaFuncAttributeMaxDynamicSharedMemorySize, SMEM32);
        cudaFuncSetAttribute(conv32_32j2<2>, cudaFuncAttributeMaxDynamicSharedMemorySize, SMEM32);
        attr_done = true;
    }

    auto ceil_div = [](int a, int b) { return (a + b - 1) / b; };
    const int T = 256;

    // ---- build inverse maps ----
    cudaMemsetAsync(gi0, 0xFF, (size_t)27 * n0 * sizeof(int), 0);
    cudaMemsetAsync(gid, 0xFF, (size_t)8 * n1 * sizeof(int), 0);
    cudaMemsetAsync(gi1, 0xFF, (size_t)27 * n1 * sizeof(int), 0);
    {
        dim3 g0(ceil_div(P0, T), 27);
        build_gi<<<g0, T>>>(km0_in, km0_out, gi0, P0, n0);
        dim3 gd(ceil_div(Pd, T), 8);
        build_gi<<<gd, T>>>(kmd_in, kmd_out, gid, Pd, n1);
        dim3 g1(ceil_div(P1, T), 27);
        build_gi<<<g1, T>>>(km1_in, km1_out, gi1, P1, n1);
    }

    conv1_16j2<<<ceil_div(n0, 512), T>>>(in_feats, W_first, gi0, b_first, x0, out_cached, n0);
    conv16_16j4<<<ceil_div(n0, 1024), T>>>(x0, W_pre, gi0, b_pre, x1, n0);
    conv16_32j2<<<ceil_div(n1, 512), T>>>(x1, W_down, gid, b_down, x2, n1);

    const int gb = ceil_div(n1, 512);
    conv32_32j2<0><<<gb, 256, SMEM32>>>(x2, W_r0, gi1, b_r0, nullptr, r0, n1);
    conv32_32j2<1><<<gb, 256, SMEM32>>>(r0, W_r1, gi1, b_r1, x2, r1, n1);
    conv32_32j2<2><<<gb, 256, SMEM32>>>(r1, W_fin, gi1, b_fin, nullptr, out_fin, n1);
}

// round 16
// speedup vs baseline: 1.0258x; 1.0258x over previous
#include <cuda_runtime.h>
#include <cstdint>

// ---------------- static scratch (no allocations allowed) ----------------
#define MAXN0 600000
__device__ float g_x0[MAXN0 * 16];
__device__ float g_x1[MAXN0 * 16];
__device__ float g_x2[MAXN0 * 32];
__device__ float g_r0[MAXN0 * 32];
__device__ float g_r1[MAXN0 * 32];
__device__ int   g_gi0[27 * MAXN0];
__device__ int   g_gid[8 * MAXN0];
__device__ int   g_gi1[27 * MAXN0];

typedef unsigned long long u64;
union F2U { u64 u; float2 f; };

__device__ __forceinline__ u64 bcast2(float s) {
    u64 r; asm("mov.b64 %0, {%1, %1};" : "=l"(r) : "r"(__float_as_uint(s))); return r;
}
__device__ __forceinline__ void ffma2(u64& a, u64 x, u64 w) {
    asm("fma.rn.f32x2 %0, %1, %2, %3;" : "=l"(a) : "l"(x), "l"(w), "l"(a));
}
__device__ __forceinline__ u64 packf2(float lo, float hi) {
    u64 r; asm("mov.b64 %0, {%1, %2};" : "=l"(r) : "r"(__float_as_uint(lo)), "r"(__float_as_uint(hi))); return r;
}

// ---------------- inverse-map build ----------------
__global__ void build_gi(const int* __restrict__ kin, const int* __restrict__ kout,
                         int* __restrict__ gi, int P, int n) {
    const int k = blockIdx.y;
    int p = blockIdx.x * blockDim.x + threadIdx.x;
    if (p >= P) return;
    const size_t base = (size_t)k * P;
    int j = kout[base + p];
    if (j < n) gi[(size_t)k * n + j] = kin[base + p];
}

// ---------------- conv 1->16: two output rows per thread (R13) ----------
__global__ __launch_bounds__(256) void conv1_16j2(const float* __restrict__ x,
        const float* __restrict__ W, const int* __restrict__ gi,
        const float* __restrict__ b, float* __restrict__ out,
        float* __restrict__ cache, int n) {
    __shared__ float Ws[27 * 16];
    for (int t = threadIdx.x; t < 27 * 16; t += 256) Ws[t] = W[t];
    __syncthreads();
    const int tid = threadIdx.x;
    const int j0 = blockIdx.x * 512 + tid;
    const int j1 = j0 + 256;
    const bool jv1 = j1 < n;
    if (j0 >= n) return;
    float acc0[16], acc1[16];
#pragma unroll
    for (int c = 0; c < 16; ++c) { float bb = __ldg(b + c); acc0[c] = bb; acc1[c] = bb; }
#pragma unroll
    for (int kb = 0; kb < 27; kb += 9) {
        int id0[9], id1[9];
#pragma unroll
        for (int t = 0; t < 9; ++t) {
            id0[t] = __ldg(gi + (size_t)(kb + t) * n + j0);
            id1[t] = jv1 ? __ldg(gi + (size_t)(kb + t) * n + j1) : -1;
        }
        float xv0[9], xv1[9];
#pragma unroll
        for (int t = 0; t < 9; ++t) {
            xv0[t] = (id0[t] >= 0) ? __ldg(x + id0[t]) : 0.f;
            xv1[t] = (id1[t] >= 0) ? __ldg(x + id1[t]) : 0.f;
        }
#pragma unroll
        for (int t = 0; t < 9; ++t) {
#pragma unroll
            for (int c = 0; c < 16; ++c) {
                acc0[c] += xv0[t] * Ws[(kb + t) * 16 + c];
                acc1[c] += xv1[t] * Ws[(kb + t) * 16 + c];
            }
        }
    }
    {
        float4* o4 = (float4*)(out + (size_t)j0 * 16);
        float4* c4 = (float4*)(cache + (size_t)j0 * 16);
#pragma unroll
        for (int r = 0; r < 4; ++r) {
            float4 v = make_float4(fmaxf(acc0[4*r], 0.f), fmaxf(acc0[4*r+1], 0.f),
                                   fmaxf(acc0[4*r+2], 0.f), fmaxf(acc0[4*r+3], 0.f));
            o4[r] = v; c4[r] = v;
        }
    }
    if (jv1) {
        float4* o4 = (float4*)(out + (size_t)j1 * 16);
        float4* c4 = (float4*)(cache + (size_t)j1 * 16);
#pragma unroll
        for (int r = 0; r < 4; ++r) {
            float4 v = make_float4(fmaxf(acc1[4*r], 0.f), fmaxf(acc1[4*r+1], 0.f),
                                   fmaxf(acc1[4*r+2], 0.f), fmaxf(acc1[4*r+3], 0.f));
            o4[r] = v; c4[r] = v;
        }
    }
}

// ====== conv 16->16 (K=27): four rows/thread (R14) ======================
__global__ __launch_bounds__(256, 2) void conv16_16j4(const float* __restrict__ x,
        const float* __restrict__ W, const int* __restrict__ gi,
        const float* __restrict__ b, float* __restrict__ out, int n) {
    __shared__ float4 Ws4[27 * 64];          // 27 KB
    const float4* Wg = (const float4*)W;
    for (int t = threadIdx.x; t < 27 * 64; t += 256) Ws4[t] = Wg[t];
    __syncthreads();
    const ulonglong2* Wu = (const ulonglong2*)Ws4;
    const int tid = threadIdx.x;
    int j[4];
    j[0] = blockIdx.x * 1024 + tid;
    j[1] = j[0] + 256; j[2] = j[0] + 512; j[3] = j[0] + 768;

    u64 acc[32];                              // 8 u64 per row
    {
        const float4* b4 = (const float4*)b;
#pragma unroll
        for (int r = 0; r < 4; ++r) {
            float4 bb = __ldg(b4 + r);
            u64 lo = packf2(bb.x, bb.y), hi = packf2(bb.z, bb.w);
#pragma unroll
            for (int o = 0; o < 4; ++o) { acc[o*8 + 2*r] = lo; acc[o*8 + 2*r + 1] = hi; }
        }
    }
    int a[4];
#pragma unroll
    for (int o = 0; o < 4; ++o) a[o] = (j[o] < n) ? __ldg(gi + j[o]) : -1;

    for (int k = 0; k < 27; ++k) {
        int i[4];
#pragma unroll
        for (int o = 0; o < 4; ++o) {
            i[o] = a[o];
            a[o] = (k < 26 && j[o] < n) ? __ldg(gi + (size_t)(k + 1) * n + j[o]) : -1;
        }
        if (!__ballot_sync(0xffffffffu, (i[0] >= 0) | (i[1] >= 0) | (i[2] >= 0) | (i[3] >= 0)))
            continue;
        const ulonglong2* Wk = Wu + (size_t)k * 64;
#pragma unroll
        for (int h = 0; h < 2; ++h) {         // input-channel halves (8 cc each)
            float4 X[4][2];
#pragma unroll
            for (int o = 0; o < 4; ++o) {
                const float4* xr = (const float4*)(x + (size_t)(i[o] < 0 ? 0 : i[o]) * 16) + h * 2;
#pragma unroll
                for (int q = 0; q < 2; ++q)
                    X[o][q] = (i[o] >= 0) ? __ldg(xr + q) : make_float4(0.f, 0.f, 0.f, 0.f);
            }
#pragma unroll
            for (int q = 0; q < 2; ++q) {
#pragma unroll
                for (int s = 0; s < 4; ++s) {
                    const int cc = h * 8 + q * 4 + s;
                    u64 xx[4];
#pragma unroll
                    for (int o = 0; o < 4; ++o) {
                        float xs = (s == 0) ? X[o][q].x : (s == 1) ? X[o][q].y
                                 : (s == 2) ? X[o][q].z : X[o][q].w;
                        xx[o] = bcast2(xs);
                    }
#pragma unroll
                    for (int r = 0; r < 4; ++r) {
                        ulonglong2 wp = Wk[cc * 4 + r];
#pragma unroll
                        for (int o = 0; o < 4; ++o) {
                            ffma2(acc[o*8 + 2*r],     xx[o], wp.x);
                            ffma2(acc[o*8 + 2*r + 1], xx[o], wp.y);
                        }
                    }
                }
            }
        }
    }
#pragma unroll
    for (int o = 0; o < 4; ++o) {
        if (j[o] >= n) continue;
        const u64* ap = acc + o * 8;
        float4* o4 = (float4*)(out + (size_t)j[o] * 16);
#pragma unroll
        for (int r = 0; r < 4; ++r) {
            F2U a0u, a1u; a0u.u = ap[2*r]; a1u.u = ap[2*r+1];
            o4[r] = make_float4(fmaxf(a0u.f.x, 0.f), fmaxf(a0u.f.y, 0.f),
                                fmaxf(a1u.f.x, 0.f), fmaxf(a1u.f.y, 0.f));
        }
    }
}

// ====== conv 16->32 (K=8, downsample): two output rows per thread =======
__global__ __launch_bounds__(256, 2) void conv16_32j2(const float* __restrict__ x,
        const float* __restrict__ W, const int* __restrict__ gi,
        const float* __restrict__ b, float* __restrict__ out, int n) {
    __shared__ float4 Ws4[8 * 128];          // 16 KB
    const float4* Wg = (const float4*)W;
    for (int t = threadIdx.x; t < 8 * 128; t += 256) Ws4[t] = Wg[t];
    __syncthreads();
    const ulonglong2* Wu = (const ulonglong2*)Ws4;
    const int tid = threadIdx.x;
    const int j0 = blockIdx.x * 512 + tid;
    const int j1 = j0 + 256;
    const bool jv0 = j0 < n, jv1 = j1 < n;

    u64 acc[32];
    {
        const float4* b4 = (const float4*)b;
#pragma unroll
        for (int r = 0; r < 8; ++r) {
            float4 bb = __ldg(b4 + r);
            u64 lo = packf2(bb.x, bb.y), hi = packf2(bb.z, bb.w);
            acc[2*r] = lo; acc[2*r+1] = hi;
            acc[16 + 2*r] = lo; acc[16 + 2*r+1] = hi;
        }
    }
    int a0 = jv0 ? __ldg(gi + j0) : -1;
    int a1 = jv1 ? __ldg(gi + j1) : -1;
    for (int k = 0; k < 8; ++k) {
        const int i0 = a0, i1 = a1;
        a0 = (k < 7 && jv0) ? __ldg(gi + (size_t)(k + 1) * n + j0) : -1;
        a1 = (k < 7 && jv1) ? __ldg(gi + (size_t)(k + 1) * n + j1) : -1;
        if (!__ballot_sync(0xffffffffu, (i0 >= 0) || (i1 >= 0))) continue;
        const float4* xr0 = (const float4*)(x + (size_t)(i0 < 0 ? 0 : i0) * 16);
        const float4* xr1 = (const float4*)(x + (size_t)(i1 < 0 ? 0 : i1) * 16);
        float4 X0[4], X1[4];
#pragma unroll
        for (int q = 0; q < 4; ++q) {
            X0[q] = (i0 >= 0) ? __ldg(xr0 + q) : make_float4(0.f, 0.f, 0.f, 0.f);
            X1[q] = (i1 >= 0) ? __ldg(xr1 + q) : make_float4(0.f, 0.f, 0.f, 0.f);
        }
        const ulonglong2* Wk = Wu + (size_t)k * 128;
#pragma unroll
        for (int q = 0; q < 4; ++q) {
            float xs0[4] = {X0[q].x, X0[q].y, X0[q].z, X0[q].w};
            float xs1[4] = {X1[q].x, X1[q].y, X1[q].z, X1[q].w};
#pragma unroll
            for (int s = 0; s < 4; ++s) {
                int cc = q * 4 + s;
                u64 xx0 = bcast2(xs0[s]);
                u64 xx1 = bcast2(xs1[s]);
#pragma unroll
                for (int r = 0; r < 8; ++r) {
                    ulonglong2 wp = Wk[cc * 8 + r];
                    ffma2(acc[2*r],          xx0, wp.x);
                    ffma2(acc[2*r + 1],      xx0, wp.y);
                    ffma2(acc[16 + 2*r],     xx1, wp.x);
                    ffma2(acc[16 + 2*r + 1], xx1, wp.y);
                }
            }
        }
    }
#pragma unroll
    for (int o = 0; o < 2; ++o) {
        const int j = o ? j1 : j0;
        if (j >= n) continue;
        const u64* a = acc + o * 16;
        float4* o4 = (float4*)(out + (size_t)j * 32);
#pragma unroll
        for (int r = 0; r < 8; ++r) {
            F2U a0u, a1u; a0u.u = a[2*r]; a1u.u = a[2*r+1];
            o4[r] = make_float4(fmaxf(a0u.f.x, 0.f), fmaxf(a0u.f.y, 0.f),
                                fmaxf(a1u.f.x, 0.f), fmaxf(a1u.f.y, 0.f));
        }
    }
}

// ====== conv 32->32 (K=27): two rows/thread, 2 CTAs/SM (R13 winner) =====
template <int EPI>   // 0 = bias+relu, 1 = bias+residual, 2 = bias only
__global__ __launch_bounds__(256, 2) void conv32_32j2(const float* __restrict__ x,
        const float* __restrict__ W, const int* __restrict__ gi,
        const float* __restrict__ b, const float* __restrict__ skip,
        float* __restrict__ out, int n) {
    extern __shared__ float4 Ws4[];          // 27 * 256 float4 = 108 KB
    const float4* Wg = (const float4*)W;
    for (int t = threadIdx.x; t < 27 * 256; t += 256) Ws4[t] = Wg[t];
    __syncthreads();
    const ulonglong2* Wu = (const ulonglong2*)Ws4;
    const int tid = threadIdx.x;
    const int j0 = blockIdx.x * 512 + tid;
    const int j1 = j0 + 256;
    const bool jv0 = j0 < n, jv1 = j1 < n;

    u64 acc[32];                              // [0..15] row j0, [16..31] row j1
    {
        const float4* b4 = (const float4*)b;
#pragma unroll
        for (int r = 0; r < 8; ++r) {
            float4 bb = __ldg(b4 + r);
            u64 lo = packf2(bb.x, bb.y), hi = packf2(bb.z, bb.w);
            acc[2*r] = lo; acc[2*r+1] = hi;
            acc[16 + 2*r] = lo; acc[16 + 2*r+1] = hi;
        }
    }
    int a0 = jv0 ? __ldg(gi + j0) : -1;
    int a1 = jv1 ? __ldg(gi + j1) : -1;
    for (int k = 0; k < 27; ++k) {
        const int i0 = a0, i1 = a1;
        a0 = (k < 26 && jv0) ? __ldg(gi + (size_t)(k + 1) * n + j0) : -1;
        a1 = (k < 26 && jv1) ? __ldg(gi + (size_t)(k + 1) * n + j1) : -1;
        if (!__ballot_sync(0xffffffffu, (i0 >= 0) || (i1 >= 0))) continue;
        const float4* xr0 = (const float4*)(x + (size_t)(i0 < 0 ? 0 : i0) * 32);
        const float4* xr1 = (const float4*)(x + (size_t)(i1 < 0 ? 0 : i1) * 32);
        const ulonglong2* Wk = Wu + (size_t)k * 256;
#pragma unroll
        for (int h = 0; h < 2; ++h) {         // input-channel halves keep regs low
            float4 X0[4], X1[4];
#pragma unroll
            for (int q = 0; q < 4; ++q) {
                X0[q] = (i0 >= 0) ? __ldg(xr0 + h * 4 + q) : make_float4(0.f, 0.f, 0.f, 0.f);
                X1[q] = (i1 >= 0) ? __ldg(xr1 + h * 4 + q) : make_float4(0.f, 0.f, 0.f, 0.f);
            }
#pragma unroll
            for (int q = 0; q < 4; ++q) {
                float xs0[4] = {X0[q].x, X0[q].y, X0[q].z, X0[q].w};
                float xs1[4] = {X1[q].x, X1[q].y, X1[q].z, X1[q].w};
#pragma unroll
                for (int s = 0; s < 4; ++s) {
                    int cc = h * 16 + q * 4 + s;
                    u64 xx0 = bcast2(xs0[s]);
                    u64 xx1 = bcast2(xs1[s]);
#pragma unroll
                    for (int r = 0; r < 8; ++r) {
                        ulonglong2 wp = Wk[cc * 8 + r];
                        ffma2(acc[2*r],          xx0, wp.x);
                        ffma2(acc[2*r + 1],      xx0, wp.y);
                        ffma2(acc[16 + 2*r],     xx1, wp.x);
                        ffma2(acc[16 + 2*r + 1], xx1, wp.y);
                    }
                }
            }
        }
    }
#pragma unroll
    for (int o = 0; o < 2; ++o) {
        const int j = o ? j1 : j0;
        if (j >= n) continue;
        const u64* a = acc + o * 16;
        float4* o4 = (float4*)(out + (size_t)j * 32);
        const float4* s4 = (EPI == 1) ? (const float4*)(skip + (size_t)j * 32) : nullptr;
#pragma unroll
        for (int r = 0; r < 8; ++r) {
            F2U a0u, a1u; a0u.u = a[2*r]; a1u.u = a[2*r+1];
            float4 v = make_float4(a0u.f.x, a0u.f.y, a1u.f.x, a1u.f.y);
            if (EPI == 0) {
                v.x = fmaxf(v.x, 0.f); v.y = fmaxf(v.y, 0.f);
                v.z = fmaxf(v.z, 0.f); v.w = fmaxf(v.w, 0.f);
            }
            if (EPI == 1) {
                float4 sv = __ldg(s4 + r);
                v.x += sv.x; v.y += sv.y; v.z += sv.z; v.w += sv.w;
            }
            o4[r] = v;
        }
    }
}

// ---------------- host orchestration ----------------
extern "C" void kernel_launch(void* const* d_in, const int* in_sizes, int n_in,
                              void* d_out, int out_size) {
    const float* in_feats = (const float*)d_in[0];
    const float* W_first  = (const float*)d_in[1];
    const float* b_first  = (const float*)d_in[2];
    const float* W_pre    = (const float*)d_in[3];
    const float* b_pre    = (const float*)d_in[4];
    const float* W_down   = (const float*)d_in[5];
    const float* b_down   = (const float*)d_in[6];
    const float* W_r0     = (const float*)d_in[7];
    const float* b_r0     = (const float*)d_in[8];
    const float* W_r1     = (const float*)d_in[9];
    const float* b_r1     = (const float*)d_in[10];
    const float* W_fin    = (const float*)d_in[11];
    const float* b_fin    = (const float*)d_in[12];
    const int* km0_in  = (const int*)d_in[13];
    const int* km0_out = (const int*)d_in[14];
    const int* kmd_in  = (const int*)d_in[15];
    const int* kmd_out = (const int*)d_in[16];
    const int* km1_in  = (const int*)d_in[17];
    const int* km1_out = (const int*)d_in[18];

    const int n0 = in_sizes[0];
    const int P0 = in_sizes[13] / 27;
    const int Pd = in_sizes[15] / 8;
    const int P1 = in_sizes[17] / 27;
    const int n1 = (out_size - n0 * 16) / 32;

    float* out_fin    = (float*)d_out;
    float* out_cached = (float*)d_out + (size_t)n1 * 32;

    float *x0, *x1, *x2, *r0, *r1;
    int *gi0, *gid, *gi1;
    cudaGetSymbolAddress((void**)&x0, g_x0);
    cudaGetSymbolAddress((void**)&x1, g_x1);
    cudaGetSymbolAddress((void**)&x2, g_x2);
    cudaGetSymbolAddress((void**)&r0, g_r0);
    cudaGetSymbolAddress((void**)&r1, g_r1);
    cudaGetSymbolAddress((void**)&gi0, g_gi0);
    cudaGetSymbolAddress((void**)&gid, g_gid);
    cudaGetSymbolAddress((void**)&gi1, g_gi1);

    const int SMEM32 = 27 * 256 * sizeof(float4);  // 110592 B
    static bool init_done = false;
    static cudaStream_t s1;
    static cudaEvent_t evFork, evJoin;
    if (!init_done) {
        cudaFuncSetAttribute(conv32_32j2<0>, cudaFuncAttributeMaxDynamicSharedMemorySize, SMEM32);
        cudaFuncSetAttribute(conv32_32j2<1>, cudaFuncAttributeMaxDynamicSharedMemorySize, SMEM32);
        cudaFuncSetAttribute(conv32_32j2<2>, cudaFuncAttributeMaxDynamicSharedMemorySize, SMEM32);
        cudaStreamCreateWithFlags(&s1, cudaStreamNonBlocking);
        cudaEventCreateWithFlags(&evFork, cudaEventDisableTiming);
        cudaEventCreateWithFlags(&evJoin, cudaEventDisableTiming);
        init_done = true;
    }

    auto ceil_div = [](int a, int b) { return (a + b - 1) / b; };
    const int T = 256;

    // ---- fork: level-1 map builds on s1, level-0 path on stream 0 ----
    cudaEventRecord(evFork, 0);
    cudaStreamWaitEvent(s1, evFork, 0);

    // s1: gid + gi1 builds (needed only from conv16_32 onward)
    cudaMemsetAsync(gid, 0xFF, (size_t)8 * n1 * sizeof(int), s1);
    cudaMemsetAsync(gi1, 0xFF, (size_t)27 * n1 * sizeof(int), s1);
    {
        dim3 gd(ceil_div(Pd, T), 8);
        build_gi<<<gd, T, 0, s1>>>(kmd_in, kmd_out, gid, Pd, n1);
        dim3 g1(ceil_div(P1, T), 27);
        build_gi<<<g1, T, 0, s1>>>(km1_in, km1_out, gi1, P1, n1);
    }
    cudaEventRecord(evJoin, s1);

    // stream 0: gi0 build + level-0 convs
    cudaMemsetAsync(gi0, 0xFF, (size_t)27 * n0 * sizeof(int), 0);
    {
        dim3 g0(ceil_div(P0, T), 27);
        build_gi<<<g0, T, 0, 0>>>(km0_in, km0_out, gi0, P0, n0);
    }
    conv1_16j2<<<ceil_div(n0, 512), T, 0, 0>>>(in_feats, W_first, gi0, b_first, x0, out_cached, n0);
    conv16_16j4<<<ceil_div(n0, 1024), T, 0, 0>>>(x0, W_pre, gi0, b_pre, x1, n0);

    // ---- join: level-1 maps must be ready ----
    cudaStreamWaitEvent(0, evJoin, 0);

    conv16_32j2<<<ceil_div(n1, 512), T, 0, 0>>>(x1, W_down, gid, b_down, x2, n1);

    const int gb = ceil_div(n1, 512);
    conv32_32j2<0><<<gb, 256, SMEM32, 0>>>(x2, W_r0, gi1, b_r0, nullptr, r0, n1);
    conv32_32j2<1><<<gb, 256, SMEM32, 0>>>(r0, W_r1, gi1, b_r1, x2, r1, n1);
    conv32_32j2<2><<<gb, 256, SMEM32, 0>>>(r1, W_fin, gi1, b_fin, nullptr, out_fin, n1);
}